// round 13
// baseline (speedup 1.0000x reference)
#include <cuda_runtime.h>
#include <cstdint>

#define IN_SIZE  256
#define N_NODES  1024
#define DEG      32
#define BATCH    16384
#define OUT_SIZE 16

#define BT      32                      // batch columns per CTA (= warp width)
#define NTHR    384                     // 12 warps -> reg cap 170/thread (no spill)
#define NWARP   12
#define NROWS   (IN_SIZE + N_NODES)     // 1280
#define NCTA    (BATCH / BT)            // 512
#define REC     13                      // uint4/node: 4 idx16 + 8 w + 1 meta
#define AS_FLOATS (NROWS * BT)          // 40960 (row stride 32 words = 128 B)
#define MAXB    1100
#define SMEM_BYTES (AS_FLOATS * 4 + (MAXB + 4) * 4)

// ---------------- device globals ----------------
__device__ int   g_sched[N_NODES];      // slot -> node id (level-grouped)
__device__ int   g_nlvl;                // number of level chunks
__device__ int   g_lvloff[MAXB];        // chunk boundaries B[0..nlvl]
__device__ uint4 g_prec[N_NODES * REC]; // slot-major packed node records

// ---------------- prepass: depth + schedule + pack (1 block, fused) ----------------
__device__ __forceinline__ int redmax32(int v) {
    int r;
    asm("redux.sync.max.s32 %0, %1, 0xffffffff;" : "=r"(r) : "r"(v));
    return r;
}

#define PA_SMEM ((32768 + 1280 + 1025 + 1025 + 2) * 4)

__global__ void schedule_kernel(const int* __restrict__ idx, const float* __restrict__ w) {
    extern __shared__ int sm[];
    int* s_idx = sm;                    // [1024*32]
    int* s_dep = sm + 32768;            // [1280] depth per activation row
    int* s_cnt = s_dep + 1280;          // [1025] level histogram
    int* s_off = s_cnt + 1025;          // [1025] level start slot (placement cursor)
    int* s_aux = s_off + 1025;          // [1]: maxd
    const int tid = threadIdx.x;

    {   // stage idx; init
        const int4* src = (const int4*)idx;
        int4* dst = (int4*)s_idx;
        for (int i = tid; i < 8192; i += 256) dst[i] = src[i];
        for (int i = tid; i < 256;  i += 256) s_dep[i] = 0;
        for (int i = tid; i < 1025; i += 256) s_cnt[i] = 0;
        if (tid == 0) s_aux[0] = 0;
    }
    __syncthreads();

    // ---- sequential depth, 4-node speculative window (warp 0) ----
    if (tid < 32) {
        const int lane = tid;
        for (int base = 0; base < N_NODES; base += 4) {
            const int lim = IN_SIZE + base;
            int r0 = s_idx[(base + 0) * 32 + lane];
            int r1 = s_idx[(base + 1) * 32 + lane];
            int r2 = s_idx[(base + 2) * 32 + lane];
            int r3 = s_idx[(base + 3) * 32 + lane];
            int v0 = (r0 < lim) ? s_dep[r0] : 0;   // in-window refs patched below
            int v1 = (r1 < lim) ? s_dep[r1] : 0;
            int v2 = (r2 < lim) ? s_dep[r2] : 0;
            int v3 = (r3 < lim) ? s_dep[r3] : 0;
            int m0 = redmax32(v0), m1 = redmax32(v1);
            int m2 = redmax32(v2), m3 = redmax32(v3);
            bool b10 = __any_sync(0xffffffffu, r1 == lim);
            bool b20 = __any_sync(0xffffffffu, r2 == lim);
            bool b21 = __any_sync(0xffffffffu, r2 == lim + 1);
            bool b30 = __any_sync(0xffffffffu, r3 == lim);
            bool b31 = __any_sync(0xffffffffu, r3 == lim + 1);
            bool b32 = __any_sync(0xffffffffu, r3 == lim + 2);
            int d0 = m0 + 1;
            int d1 = max(m1, b10 ? d0 : 0) + 1;
            int d2 = max(max(m2, b20 ? d0 : 0), b21 ? d1 : 0) + 1;
            int d3 = max(max(m3, b30 ? d0 : 0), max(b31 ? d1 : 0, b32 ? d2 : 0)) + 1;
            if (lane == 0) {
                s_dep[lim]     = d0;  s_dep[lim + 1] = d1;
                s_dep[lim + 2] = d2;  s_dep[lim + 3] = d3;
            }
            __syncwarp();   // order lane0's STS before next window's cross-lane LDS
        }
    }
    __syncthreads();

    // ---- level histogram + max level ----
    for (int i = tid; i < N_NODES; i += 256) {
        int l = s_dep[IN_SIZE + i];
        atomicAdd(&s_cnt[l], 1);
        atomicMax(&s_aux[0], l);
    }
    __syncthreads();

    // ---- level boundaries (one chunk per nonempty level) ----
    if (tid == 0) {
        int acc = 0, nb = 0, md = s_aux[0];
        g_lvloff[0] = 0;
        for (int l = 1; l <= md; l++) {
            s_off[l] = acc;
            int c = s_cnt[l];
            if (c > 0) { acc += c; g_lvloff[++nb] = acc; }
        }
        g_nlvl = nb;
    }
    __syncthreads();

    // ---- stable placement (warp 0, match_any) ----
    if (tid < 32) {
        const int lane = tid;
        for (int c = 0; c < 32; c++) {
            int i = c * 32 + lane;
            int l = s_dep[IN_SIZE + i];
            unsigned mask = __match_any_sync(0xffffffffu, l);
            int rank = __popc(mask & ((1u << lane) - 1u));
            int base_ = s_off[l];
            g_sched[base_ + rank] = i;
            if ((int)(__ffs(mask) - 1) == lane) s_off[l] = base_ + __popc(mask);
            __syncwarp();
        }
    }
    __syncthreads();

    // ---- fused pack, 13-uint4 records ----
    // j=0..3 : 8 packed idx16 each; idx16 = row<<2; u32 = idx16(2t) | idx16(2t+1)<<16
    // j=4..11: weights f32, W[j-4].c = w[(j-4)*4 + c]
    // j=12   : { store byte offset, 0,0,0 }
    for (int e = tid; e < N_NODES * REC; e += 256) {
        int s = e / REC, j = e - s * REC;
        int node = g_sched[s];
        const int* ni = s_idx + node * DEG;
        if (j < 4) {
            unsigned p[4];
            #pragma unroll
            for (int c = 0; c < 4; c++) {
                int t = j * 4 + c;          // covers degrees 2t, 2t+1
                unsigned lo = (unsigned)ni[2 * t]     << 2;
                unsigned hi = (unsigned)ni[2 * t + 1] << 2;
                p[c] = lo | (hi << 16);
            }
            g_prec[e] = make_uint4(p[0], p[1], p[2], p[3]);
        } else if (j < 12) {
            int d0 = (j - 4) * 4;
            g_prec[e] = make_uint4(__float_as_uint(w[node * DEG + d0 + 0]),
                                   __float_as_uint(w[node * DEG + d0 + 1]),
                                   __float_as_uint(w[node * DEG + d0 + 2]),
                                   __float_as_uint(w[node * DEG + d0 + 3]));
        } else {
            g_prec[e] = make_uint4((unsigned)(IN_SIZE + node) << 7, 0u, 0u, 0u);
        }
    }
}

// Exact tanh(x) = 1 - 2/(exp(2x)+1); ~1e-6 abs err, saturates correctly.
__device__ __forceinline__ float ftanh(float x) {
    float e = __expf(2.0f * x);
    return 1.0f - __fdividef(2.0f, e + 1.0f);
}

extern __shared__ float SM[];

__global__ void __launch_bounds__(NTHR, 1)
ne_kernel(const float* __restrict__ x, float* __restrict__ out) {
    const int tid  = threadIdx.x;
    const int lane = tid & 31;
    const int wid  = tid >> 5;
    const int b0   = blockIdx.x * BT;

    float* As   = SM;                       // [1280][32] floats, row = 128 B
    int*   s_lv = (int*)(SM + AS_FLOATS);   // level boundaries

    const int nb = g_nlvl;

    // ---- stage inputs transposed: As[row][col] = x[b0+col][row]; cache boundaries ----
    {
        for (int t = tid; t < BT * (IN_SIZE / 4); t += NTHR) {
            int bl = t >> 6;            // 0..31 column
            int k  = t & 63;            // float4 chunk within row
            float4 v = ((const float4*)(x + (size_t)(b0 + bl) * IN_SIZE))[k];
            int i = k * 4;
            As[(i + 0) * BT + bl] = v.x;
            As[(i + 1) * BT + bl] = v.y;
            As[(i + 2) * BT + bl] = v.z;
            As[(i + 3) * BT + bl] = v.w;
        }
        for (int i = tid; i <= nb; i += NTHR) s_lv[i] = g_lvloff[i];
    }
    __syncthreads();

    char* Acb = (char*)As + (lane << 2);    // this lane's column base

    // ---- slot walker: this warp's slots are {s_lv[k]+wid, +NWARP, ...} per level ----
    int ck = 0, csl = wid;                  // s_lv[0] == 0
    while (ck < nb && csl >= s_lv[ck + 1]) {
        ck++;
        csl = (ck < nb) ? (s_lv[ck] + wid) : -1;
    }
    if (ck >= nb) { ck = nb; csl = -1; }

    // record registers (REC=13 uint4 -> 52 regs; NTHR=384 => cap 170, no spill)
    uint4 R[REC];
    if (csl >= 0) {
        const uint4* __restrict__ P = g_prec + csl * REC;
        #pragma unroll
        for (int j = 0; j < REC; j++) R[j] = __ldg(P + j);
    }

    // ---- level loop: one warp per node; records direct from L2 via uniform LDG ----
    for (int k = 0; k < nb; k++) {
        while (ck == k) {
            // compute current node from R
            unsigned so = R[12].x;
            unsigned iv[16] = { R[0].x, R[0].y, R[0].z, R[0].w,
                                R[1].x, R[1].y, R[1].z, R[1].w,
                                R[2].x, R[2].y, R[2].z, R[2].w,
                                R[3].x, R[3].y, R[3].z, R[3].w };
            float a0 = 0.f, a1 = 0.f, a2 = 0.f, a3 = 0.f;
            #pragma unroll
            for (int t = 0; t < 16; t += 2) {
                uint4 W = R[4 + (t >> 1)];          // 4 weights for degrees 2t..2t+3
                unsigned va = iv[t], vb = iv[t + 1];
                float x0 = *(const float*)(Acb + ((va & 0xffffu) << 5));
                float x1 = *(const float*)(Acb + ((va >> 16) << 5));
                float x2 = *(const float*)(Acb + ((vb & 0xffffu) << 5));
                float x3 = *(const float*)(Acb + ((vb >> 16) << 5));
                a0 = __fmaf_rn(__uint_as_float(W.x), x0, a0);
                a1 = __fmaf_rn(__uint_as_float(W.y), x1, a1);
                a2 = __fmaf_rn(__uint_as_float(W.z), x2, a2);
                a3 = __fmaf_rn(__uint_as_float(W.w), x3, a3);
            }
            float t = ftanh((a0 + a2) + (a1 + a3));
            *(float*)((char*)As + so + (lane << 2)) = t;    // conflict-free row store

            // advance walker and immediately load next record (L2 latency
            // covered by the other 2 warps on this SMSP computing)
            csl += NWARP;
            while (csl >= s_lv[ck + 1]) {
                ck++;
                if (ck >= nb) { csl = -1; break; }
                csl = s_lv[ck] + wid;
            }
            if (csl >= 0) {
                const uint4* __restrict__ P = g_prec + csl * REC;
                #pragma unroll
                for (int j = 0; j < REC; j++) R[j] = __ldg(P + j);
            }
        }
        __syncthreads();
    }

    // ---- emit last OUT_SIZE node rows (by original id): out[o][b0+c] ----
    for (int e = tid; e < OUT_SIZE * BT; e += NTHR) {
        int o = e >> 5, c = e & 31;
        float v = As[(IN_SIZE + N_NODES - OUT_SIZE + o) * BT + c];
        out[(size_t)o * BATCH + b0 + c] = v;
    }
}

extern "C" void kernel_launch(void* const* d_in, const int* in_sizes, int n_in,
                              void* d_out, int out_size) {
    const float* x   = (const float*)d_in[0];   // [16384, 256] f32
    const float* w   = (const float*)d_in[1];   // [1024, 32]   f32
    const int*   idx = (const int*)  d_in[2];   // [1024, 32]   i32
    float*       out = (float*)d_out;           // [16, 16384]  f32

    cudaFuncSetAttribute(schedule_kernel, cudaFuncAttributeMaxDynamicSharedMemorySize, PA_SMEM);
    cudaFuncSetAttribute(ne_kernel, cudaFuncAttributeMaxDynamicSharedMemorySize, SMEM_BYTES);

    schedule_kernel<<<1, 256, PA_SMEM>>>(idx, w);
    ne_kernel<<<NCTA, NTHR, SMEM_BYTES>>>(x, out);
}

// round 14
// speedup vs baseline: 1.2751x; 1.2751x over previous
#include <cuda_runtime.h>
#include <cstdint>

#define IN_SIZE  256
#define N_NODES  1024
#define DEG      32
#define BATCH    16384
#define OUT_SIZE 16

#define BT      32                      // batch columns per CTA (= warp width)
#define NTHR    384                     // 12 warps (R8-proven optimum)
#define NWARP   12
#define NROWS   (IN_SIZE + N_NODES)     // 1280
#define NCTA    (BATCH / BT)            // 512
#define REC     17                      // uint4/node: 16 (off,w,off,w) + 1 meta
#define PB_NODES 64                     // max nodes per level chunk
#define PB_U4   (PB_NODES * REC)        // 1088 uint4 per buffer
#define AS_FLOATS (NROWS * BT)          // 40960 (row stride 32 words = 128 B)
#define MAXB    1100
// layout: As | pbuf(2) | mbar(2 u64) | s_lv
#define SMEM_BYTES (AS_FLOATS * 4 + 2 * PB_U4 * 16 + 16 + (MAXB + 4) * 4)

// ---------------- device globals ----------------
__device__ int   g_sched[N_NODES];      // slot -> node id (level-grouped)
__device__ int   g_nlvl;                // number of level chunks
__device__ int   g_lvloff[MAXB];        // chunk boundaries B[0..nlvl]
__device__ uint4 g_prec[N_NODES * REC]; // slot-major packed node records

// ---------------- prepass: depth + schedule + pack (1 block, 1024 thr) ----------------
__device__ __forceinline__ int redmax32(int v) {
    int r;
    asm("redux.sync.max.s32 %0, %1, 0xffffffff;" : "=r"(r) : "r"(v));
    return r;
}

#define PA_NTHR 1024
#define PA_SMEM ((32768 + 1280 + 1025 + 1025 + 2) * 4)

__global__ void schedule_kernel(const int* __restrict__ idx, const float* __restrict__ w) {
    extern __shared__ int sm[];
    int* s_idx = sm;                    // [1024*32]
    int* s_dep = sm + 32768;            // [1280] depth per activation row
    int* s_cnt = s_dep + 1280;          // [1025] level histogram
    int* s_off = s_cnt + 1025;          // [1025] level start slot (placement cursor)
    int* s_aux = s_off + 1025;          // [1]: maxd
    const int tid = threadIdx.x;

    {   // stage idx; init
        const int4* src = (const int4*)idx;
        int4* dst = (int4*)s_idx;
        for (int i = tid; i < 8192; i += PA_NTHR) dst[i] = src[i];
        if (tid < 256)  s_dep[tid] = 0;
        for (int i = tid; i < 1025; i += PA_NTHR) s_cnt[i] = 0;
        if (tid == 0) s_aux[0] = 0;
    }
    __syncthreads();

    // ---- sequential depth, 4-node speculative window (warp 0) ----
    if (tid < 32) {
        const int lane = tid;
        for (int base = 0; base < N_NODES; base += 4) {
            const int lim = IN_SIZE + base;
            int r0 = s_idx[(base + 0) * 32 + lane];
            int r1 = s_idx[(base + 1) * 32 + lane];
            int r2 = s_idx[(base + 2) * 32 + lane];
            int r3 = s_idx[(base + 3) * 32 + lane];
            int v0 = (r0 < lim) ? s_dep[r0] : 0;   // in-window refs patched below
            int v1 = (r1 < lim) ? s_dep[r1] : 0;
            int v2 = (r2 < lim) ? s_dep[r2] : 0;
            int v3 = (r3 < lim) ? s_dep[r3] : 0;
            int m0 = redmax32(v0), m1 = redmax32(v1);
            int m2 = redmax32(v2), m3 = redmax32(v3);
            bool b10 = __any_sync(0xffffffffu, r1 == lim);
            bool b20 = __any_sync(0xffffffffu, r2 == lim);
            bool b21 = __any_sync(0xffffffffu, r2 == lim + 1);
            bool b30 = __any_sync(0xffffffffu, r3 == lim);
            bool b31 = __any_sync(0xffffffffu, r3 == lim + 1);
            bool b32 = __any_sync(0xffffffffu, r3 == lim + 2);
            int d0 = m0 + 1;
            int d1 = max(m1, b10 ? d0 : 0) + 1;
            int d2 = max(max(m2, b20 ? d0 : 0), b21 ? d1 : 0) + 1;
            int d3 = max(max(m3, b30 ? d0 : 0), max(b31 ? d1 : 0, b32 ? d2 : 0)) + 1;
            if (lane == 0) {
                s_dep[lim]     = d0;  s_dep[lim + 1] = d1;
                s_dep[lim + 2] = d2;  s_dep[lim + 3] = d3;
            }
            __syncwarp();   // order lane0's STS before next window's cross-lane LDS
        }
    }
    __syncthreads();

    // ---- level histogram + max level ----
    if (tid < N_NODES) {
        int l = s_dep[IN_SIZE + tid];
        atomicAdd(&s_cnt[l], 1);
        atomicMax(&s_aux[0], l);
    }
    __syncthreads();

    // ---- level starts + chunked boundaries (<= PB_NODES per chunk) ----
    if (tid == 0) {
        int acc = 0, nb = 0, md = s_aux[0];
        g_lvloff[0] = 0;
        for (int l = 1; l <= md; l++) {
            s_off[l] = acc;
            int c = s_cnt[l];
            while (c > 0) {
                int take = (c < PB_NODES) ? c : PB_NODES;
                acc += take;  c -= take;
                g_lvloff[++nb] = acc;
            }
        }
        g_nlvl = nb;
    }
    __syncthreads();

    // ---- stable placement (warp 0, match_any) ----
    if (tid < 32) {
        const int lane = tid;
        for (int c = 0; c < 32; c++) {
            int i = c * 32 + lane;
            int l = s_dep[IN_SIZE + i];
            unsigned mask = __match_any_sync(0xffffffffu, l);
            int rank = __popc(mask & ((1u << lane) - 1u));
            int base_ = s_off[l];
            g_sched[base_ + rank] = i;
            if ((int)(__ffs(mask) - 1) == lane) s_off[l] = base_ + __popc(mask);
            __syncwarp();
        }
    }
    __syncthreads();

    // ---- fused pack, 17-uint4 records (R8 format) ----
    // j<16: { off(2j), w(2j), off(2j+1), w(2j+1) }, off = row*128 (byte offset)
    // j=16: { store byte offset, 0,0,0 }
    for (int e = tid; e < N_NODES * REC; e += PA_NTHR) {
        int s = e / REC, j = e - s * REC;
        int node = g_sched[s];
        if (j < 16) {
            int d0 = 2 * j;
            g_prec[e] = make_uint4((unsigned)s_idx[node * DEG + d0]     << 7,
                                   __float_as_uint(w[node * DEG + d0]),
                                   (unsigned)s_idx[node * DEG + d0 + 1] << 7,
                                   __float_as_uint(w[node * DEG + d0 + 1]));
        } else {
            g_prec[e] = make_uint4((unsigned)(IN_SIZE + node) << 7, 0u, 0u, 0u);
        }
    }
}

// Exact tanh(x) = 1 - 2/(exp(2x)+1); ~1e-6 abs err, saturates correctly.
__device__ __forceinline__ float ftanh(float x) {
    float e = __expf(2.0f * x);
    return 1.0f - __fdividef(2.0f, e + 1.0f);
}

// ---- TMA bulk + mbarrier helpers ----
__device__ __forceinline__ void mbar_init(unsigned bar, unsigned cnt) {
    asm volatile("mbarrier.init.shared.b64 [%0], %1;" :: "r"(bar), "r"(cnt) : "memory");
}
__device__ __forceinline__ void mbar_expect_tx(unsigned bar, unsigned bytes) {
    asm volatile("mbarrier.arrive.expect_tx.shared.b64 _, [%0], %1;"
                 :: "r"(bar), "r"(bytes) : "memory");
}
__device__ __forceinline__ void mbar_wait(unsigned bar, unsigned phase) {
    asm volatile(
        "{\n\t.reg .pred P;\n"
        "WAIT_%=:\n\t"
        "mbarrier.try_wait.parity.acquire.cta.shared::cta.b64 P, [%0], %1;\n\t"
        "@P bra DONE_%=;\n\t"
        "bra WAIT_%=;\n"
        "DONE_%=:\n\t}"
        :: "r"(bar), "r"(phase) : "memory");
}
__device__ __forceinline__ void tma_bulk(unsigned dst, const void* src,
                                         unsigned bytes, unsigned bar) {
    asm volatile(
        "cp.async.bulk.shared::cta.global.mbarrier::complete_tx::bytes [%0], [%1], %2, [%3];"
        :: "r"(dst), "l"(src), "r"(bytes), "r"(bar) : "memory");
}

extern __shared__ float SM[];

__global__ void __launch_bounds__(NTHR, 1)
ne_kernel(const float* __restrict__ x, float* __restrict__ out) {
    const int tid  = threadIdx.x;
    const int lane = tid & 31;
    const int wid  = tid >> 5;
    const int b0   = blockIdx.x * BT;

    float* As   = SM;                                   // [1280][32] floats, row = 128 B
    uint4* pbuf = (uint4*)(SM + AS_FLOATS);             // 2 x PB_U4
    unsigned sm_base = (unsigned)__cvta_generic_to_shared(SM);
    const unsigned pbuf_u32 = sm_base + AS_FLOATS * 4;
    const unsigned bar0 = pbuf_u32 + 2 * PB_U4 * 16;    // 16B-aligned
    const unsigned bar1 = bar0 + 8;
    int* s_lv = (int*)((char*)pbuf + 2 * PB_U4 * 16 + 16);

    const int nb = g_nlvl;

    if (tid == 0) { mbar_init(bar0, 1); mbar_init(bar1, 1); }

    // ---- stage inputs transposed: As[row][col] = x[b0+col][row]; cache boundaries ----
    {
        for (int t = tid; t < BT * (IN_SIZE / 4); t += NTHR) {
            int bl = t >> 6;            // 0..31 column
            int k  = t & 63;            // float4 chunk within row
            float4 v = ((const float4*)(x + (size_t)(b0 + bl) * IN_SIZE))[k];
            int i = k * 4;
            As[(i + 0) * BT + bl] = v.x;
            As[(i + 1) * BT + bl] = v.y;
            As[(i + 2) * BT + bl] = v.z;
            As[(i + 3) * BT + bl] = v.w;
        }
        for (int i = tid; i <= nb; i += NTHR) s_lv[i] = g_lvloff[i];
    }
    __syncthreads();   // mbar init + staged data visible to all

    char* Acb = (char*)As + (lane << 2);    // this lane's column base

    // ---- prologue: TMA chunk 0 into buffer 0 ----
    if (tid == 0) {
        unsigned bytes = (unsigned)(s_lv[1] - s_lv[0]) * (REC * 16);
        mbar_expect_tx(bar0, bytes);
        tma_bulk(pbuf_u32, g_prec, bytes, bar0);
    }

    // ---- level-chunk loop ----
    for (int k = 0; k < nb; k++) {
        // stage next chunk into the other buffer (overlapped with compute)
        if (tid == 0 && k + 1 < nb) {
            int t0 = s_lv[k + 1], t1 = s_lv[k + 2];
            unsigned bytes = (unsigned)(t1 - t0) * (REC * 16);
            unsigned b = ((k + 1) & 1) ? bar1 : bar0;
            mbar_expect_tx(b, bytes);
            tma_bulk(pbuf_u32 + ((k + 1) & 1) * (PB_U4 * 16), g_prec + t0 * REC, bytes, b);
        }

        // wait for this chunk's records
        mbar_wait((k & 1) ? bar1 : bar0, (k >> 1) & 1);

        // compute this chunk: one warp per node, lane = column.
        // Next-slot record head is prefetched into registers BEFORE the
        // activation store so its LDS issues under the current tanh chain.
        int s0 = s_lv[k], s1 = s_lv[k + 1];
        const uint4* rec = pbuf + (k & 1) * PB_U4;
        int sl = s0 + wid;
        if (sl < s1) {
            const uint4* P = rec + (sl - s0) * REC;
            uint4 I0 = P[0], I1 = P[1], I2 = P[2], I3 = P[3];
            unsigned so = P[16].x;
            while (true) {
                int nsl = sl + NWARP;
                const uint4* Q = rec + (nsl - s0) * REC;
                uint4 J0, J1, J2, J3; unsigned nso = 0;
                if (nsl < s1) {
                    J0 = Q[0]; J1 = Q[1]; J2 = Q[2]; J3 = Q[3]; nso = Q[16].x;
                } else {
                    J0 = J1 = J2 = J3 = make_uint4(0u, 0u, 0u, 0u);
                }

                float a0, a1, a2, a3;
                // degrees 0..7 from prefetched regs
                a0 = __uint_as_float(I0.y) * *(const float*)(Acb + I0.x);
                a1 = __uint_as_float(I0.w) * *(const float*)(Acb + I0.z);
                a2 = __uint_as_float(I1.y) * *(const float*)(Acb + I1.x);
                a3 = __uint_as_float(I1.w) * *(const float*)(Acb + I1.z);
                a0 = __fmaf_rn(__uint_as_float(I2.y), *(const float*)(Acb + I2.x), a0);
                a1 = __fmaf_rn(__uint_as_float(I2.w), *(const float*)(Acb + I2.z), a1);
                a2 = __fmaf_rn(__uint_as_float(I3.y), *(const float*)(Acb + I3.x), a2);
                a3 = __fmaf_rn(__uint_as_float(I3.w), *(const float*)(Acb + I3.z), a3);
                // degrees 8..31 from SMEM record
                #pragma unroll
                for (int j = 4; j < 16; j += 2) {
                    uint4 p = P[j], q = P[j + 1];
                    a0 = __fmaf_rn(__uint_as_float(p.y), *(const float*)(Acb + p.x), a0);
                    a1 = __fmaf_rn(__uint_as_float(p.w), *(const float*)(Acb + p.z), a1);
                    a2 = __fmaf_rn(__uint_as_float(q.y), *(const float*)(Acb + q.x), a2);
                    a3 = __fmaf_rn(__uint_as_float(q.w), *(const float*)(Acb + q.z), a3);
                }
                float t = ftanh((a0 + a2) + (a1 + a3));
                *(float*)((char*)As + so + (lane << 2)) = t;    // conflict-free row store

                if (nsl >= s1) break;
                sl = nsl;  P = Q;
                I0 = J0; I1 = J1; I2 = J2; I3 = J3;  so = nso;
            }
        }

        __syncthreads();
    }

    // ---- emit last OUT_SIZE node rows (by original id): out[o][b0+c] ----
    for (int e = tid; e < OUT_SIZE * BT; e += NTHR) {
        int o = e >> 5, c = e & 31;
        float v = As[(IN_SIZE + N_NODES - OUT_SIZE + o) * BT + c];
        out[(size_t)o * BATCH + b0 + c] = v;
    }
}

extern "C" void kernel_launch(void* const* d_in, const int* in_sizes, int n_in,
                              void* d_out, int out_size) {
    const float* x   = (const float*)d_in[0];   // [16384, 256] f32
    const float* w   = (const float*)d_in[1];   // [1024, 32]   f32
    const int*   idx = (const int*)  d_in[2];   // [1024, 32]   i32
    float*       out = (float*)d_out;           // [16, 16384]  f32

    cudaFuncSetAttribute(schedule_kernel, cudaFuncAttributeMaxDynamicSharedMemorySize, PA_SMEM);
    cudaFuncSetAttribute(ne_kernel, cudaFuncAttributeMaxDynamicSharedMemorySize, SMEM_BYTES);

    schedule_kernel<<<1, PA_NTHR, PA_SMEM>>>(idx, w);
    ne_kernel<<<NCTA, NTHR, SMEM_BYTES>>>(x, out);
}

// round 15
// speedup vs baseline: 1.2820x; 1.0054x over previous
#include <cuda_runtime.h>
#include <cstdint>

#define IN_SIZE  256
#define N_NODES  1024
#define DEG      32
#define BATCH    16384
#define OUT_SIZE 16

#define BT      32                      // batch columns per CTA (= warp width)
#define NTHR    384                     // 12 warps (R8-proven optimum)
#define NWARP   12
#define NROWS   (IN_SIZE + N_NODES)     // 1280
#define NCTA    (BATCH / BT)            // 512
#define REC     17                      // uint4/node: 16 (off,w,off,w) + 1 meta
#define PB_NODES 64                     // max nodes per level chunk
#define PB_U4   (PB_NODES * REC)        // 1088 uint4 per buffer
#define AS_FLOATS (NROWS * BT)          // 40960 (row stride 32 words = 128 B)
#define MAXB    1100
// layout: As | pbuf(2) | mbar(2 u64) | s_lv
#define SMEM_BYTES (AS_FLOATS * 4 + 2 * PB_U4 * 16 + 16 + (MAXB + 4) * 4)

// ---------------- device globals ----------------
__device__ int   g_sched[N_NODES];      // slot -> node id (level-grouped)
__device__ int   g_nlvl;                // number of level chunks
__device__ int   g_lvloff[MAXB];        // chunk boundaries B[0..nlvl]
__device__ uint4 g_prec[N_NODES * REC]; // slot-major packed node records

// ---------------- prepass: depth + schedule + pack (1 block, 1024 thr) ----------------
__device__ __forceinline__ int redmax32(int v) {
    int r;
    asm("redux.sync.max.s32 %0, %1, 0xffffffff;" : "=r"(r) : "r"(v));
    return r;
}

#define PA_NTHR 1024
#define PA_SMEM ((32768 + 1280 + 1025 + 1025 + 2) * 4)

__global__ void schedule_kernel(const int* __restrict__ idx, const float* __restrict__ w) {
    extern __shared__ int sm[];
    int* s_idx = sm;                    // [1024*32]
    int* s_dep = sm + 32768;            // [1280] depth per activation row
    int* s_cnt = s_dep + 1280;          // [1025] level histogram
    int* s_off = s_cnt + 1025;          // [1025] level start slot (placement cursor)
    int* s_aux = s_off + 1025;          // [1]: maxd
    const int tid = threadIdx.x;

    {   // stage idx; init
        const int4* src = (const int4*)idx;
        int4* dst = (int4*)s_idx;
        for (int i = tid; i < 8192; i += PA_NTHR) dst[i] = src[i];
        if (tid < 256)  s_dep[tid] = 0;
        for (int i = tid; i < 1025; i += PA_NTHR) s_cnt[i] = 0;
        if (tid == 0) s_aux[0] = 0;
    }
    __syncthreads();

    // ---- sequential depth, 4-node speculative window (warp 0) ----
    if (tid < 32) {
        const int lane = tid;
        for (int base = 0; base < N_NODES; base += 4) {
            const int lim = IN_SIZE + base;
            int r0 = s_idx[(base + 0) * 32 + lane];
            int r1 = s_idx[(base + 1) * 32 + lane];
            int r2 = s_idx[(base + 2) * 32 + lane];
            int r3 = s_idx[(base + 3) * 32 + lane];
            int v0 = (r0 < lim) ? s_dep[r0] : 0;   // in-window refs patched below
            int v1 = (r1 < lim) ? s_dep[r1] : 0;
            int v2 = (r2 < lim) ? s_dep[r2] : 0;
            int v3 = (r3 < lim) ? s_dep[r3] : 0;
            int m0 = redmax32(v0), m1 = redmax32(v1);
            int m2 = redmax32(v2), m3 = redmax32(v3);
            bool b10 = __any_sync(0xffffffffu, r1 == lim);
            bool b20 = __any_sync(0xffffffffu, r2 == lim);
            bool b21 = __any_sync(0xffffffffu, r2 == lim + 1);
            bool b30 = __any_sync(0xffffffffu, r3 == lim);
            bool b31 = __any_sync(0xffffffffu, r3 == lim + 1);
            bool b32 = __any_sync(0xffffffffu, r3 == lim + 2);
            int d0 = m0 + 1;
            int d1 = max(m1, b10 ? d0 : 0) + 1;
            int d2 = max(max(m2, b20 ? d0 : 0), b21 ? d1 : 0) + 1;
            int d3 = max(max(m3, b30 ? d0 : 0), max(b31 ? d1 : 0, b32 ? d2 : 0)) + 1;
            if (lane == 0) {
                s_dep[lim]     = d0;  s_dep[lim + 1] = d1;
                s_dep[lim + 2] = d2;  s_dep[lim + 3] = d3;
            }
            __syncwarp();   // order lane0's STS before next window's cross-lane LDS
        }
    }
    __syncthreads();

    // ---- level histogram + max level ----
    if (tid < N_NODES) {
        int l = s_dep[IN_SIZE + tid];
        atomicAdd(&s_cnt[l], 1);
        atomicMax(&s_aux[0], l);
    }
    __syncthreads();

    // ---- level starts + chunked boundaries (<= PB_NODES per chunk) ----
    if (tid == 0) {
        int acc = 0, nb = 0, md = s_aux[0];
        g_lvloff[0] = 0;
        for (int l = 1; l <= md; l++) {
            s_off[l] = acc;
            int c = s_cnt[l];
            while (c > 0) {
                int take = (c < PB_NODES) ? c : PB_NODES;
                acc += take;  c -= take;
                g_lvloff[++nb] = acc;
            }
        }
        g_nlvl = nb;
    }
    __syncthreads();

    // ---- stable placement (warp 0, match_any) ----
    if (tid < 32) {
        const int lane = tid;
        for (int c = 0; c < 32; c++) {
            int i = c * 32 + lane;
            int l = s_dep[IN_SIZE + i];
            unsigned mask = __match_any_sync(0xffffffffu, l);
            int rank = __popc(mask & ((1u << lane) - 1u));
            int base_ = s_off[l];
            g_sched[base_ + rank] = i;
            if ((int)(__ffs(mask) - 1) == lane) s_off[l] = base_ + __popc(mask);
            __syncwarp();
        }
    }
    __syncthreads();

    // ---- fused pack, 17-uint4 records (R8 format) ----
    // j<16: { off(2j), w(2j), off(2j+1), w(2j+1) }, off = row*128 (byte offset)
    // j=16: { store byte offset, 0,0,0 }
    for (int e = tid; e < N_NODES * REC; e += PA_NTHR) {
        int s = e / REC, j = e - s * REC;
        int node = g_sched[s];
        if (j < 16) {
            int d0 = 2 * j;
            g_prec[e] = make_uint4((unsigned)s_idx[node * DEG + d0]     << 7,
                                   __float_as_uint(w[node * DEG + d0]),
                                   (unsigned)s_idx[node * DEG + d0 + 1] << 7,
                                   __float_as_uint(w[node * DEG + d0 + 1]));
        } else {
            g_prec[e] = make_uint4((unsigned)(IN_SIZE + node) << 7, 0u, 0u, 0u);
        }
    }
}

// Exact tanh(x) = 1 - 2/(exp(2x)+1); ~1e-6 abs err, saturates correctly.
__device__ __forceinline__ float ftanh(float x) {
    float e = __expf(2.0f * x);
    return 1.0f - __fdividef(2.0f, e + 1.0f);
}

// ---- TMA bulk + mbarrier helpers ----
__device__ __forceinline__ void mbar_init(unsigned bar, unsigned cnt) {
    asm volatile("mbarrier.init.shared.b64 [%0], %1;" :: "r"(bar), "r"(cnt) : "memory");
}
__device__ __forceinline__ void mbar_expect_tx(unsigned bar, unsigned bytes) {
    asm volatile("mbarrier.arrive.expect_tx.shared.b64 _, [%0], %1;"
                 :: "r"(bar), "r"(bytes) : "memory");
}
__device__ __forceinline__ void mbar_wait(unsigned bar, unsigned phase) {
    asm volatile(
        "{\n\t.reg .pred P;\n"
        "WAIT_%=:\n\t"
        "mbarrier.try_wait.parity.acquire.cta.shared::cta.b64 P, [%0], %1;\n\t"
        "@P bra DONE_%=;\n\t"
        "bra WAIT_%=;\n"
        "DONE_%=:\n\t}"
        :: "r"(bar), "r"(phase) : "memory");
}
__device__ __forceinline__ void tma_bulk(unsigned dst, const void* src,
                                         unsigned bytes, unsigned bar) {
    asm volatile(
        "cp.async.bulk.shared::cta.global.mbarrier::complete_tx::bytes [%0], [%1], %2, [%3];"
        :: "r"(dst), "l"(src), "r"(bytes), "r"(bar) : "memory");
}

extern __shared__ float SM[];

__global__ void __launch_bounds__(NTHR, 1)
ne_kernel(const float* __restrict__ x, float* __restrict__ out) {
    const int tid  = threadIdx.x;
    const int lane = tid & 31;
    const int wid  = tid >> 5;
    const int b0   = blockIdx.x * BT;

    float* As   = SM;                                   // [1280][32] floats, row = 128 B
    uint4* pbuf = (uint4*)(SM + AS_FLOATS);             // 2 x PB_U4
    unsigned sm_base = (unsigned)__cvta_generic_to_shared(SM);
    const unsigned pbuf_u32 = sm_base + AS_FLOATS * 4;
    const unsigned bar0 = pbuf_u32 + 2 * PB_U4 * 16;    // 16B-aligned
    const unsigned bar1 = bar0 + 8;
    int* s_lv = (int*)((char*)pbuf + 2 * PB_U4 * 16 + 16);

    const int nb = g_nlvl;

    if (tid == 0) { mbar_init(bar0, 1); mbar_init(bar1, 1); }

    // ---- stage inputs transposed: As[row][col] = x[b0+col][row]; cache boundaries ----
    {
        for (int t = tid; t < BT * (IN_SIZE / 4); t += NTHR) {
            int bl = t >> 6;            // 0..31 column
            int k  = t & 63;            // float4 chunk within row
            float4 v = ((const float4*)(x + (size_t)(b0 + bl) * IN_SIZE))[k];
            int i = k * 4;
            As[(i + 0) * BT + bl] = v.x;
            As[(i + 1) * BT + bl] = v.y;
            As[(i + 2) * BT + bl] = v.z;
            As[(i + 3) * BT + bl] = v.w;
        }
        for (int i = tid; i <= nb; i += NTHR) s_lv[i] = g_lvloff[i];
    }
    __syncthreads();   // mbar init + staged data visible to all

    char* Acb = (char*)As + (lane << 2);    // this lane's column base

    // ---- prologue: TMA chunk 0 into buffer 0 ----
    if (tid == 0) {
        unsigned bytes = (unsigned)(s_lv[1] - s_lv[0]) * (REC * 16);
        mbar_expect_tx(bar0, bytes);
        tma_bulk(pbuf_u32, g_prec, bytes, bar0);
    }

    // ---- level-chunk loop ----
    for (int k = 0; k < nb; k++) {
        // stage next chunk into the other buffer (overlapped with compute)
        if (tid == 0 && k + 1 < nb) {
            int t0 = s_lv[k + 1], t1 = s_lv[k + 2];
            unsigned bytes = (unsigned)(t1 - t0) * (REC * 16);
            unsigned b = ((k + 1) & 1) ? bar1 : bar0;
            mbar_expect_tx(b, bytes);
            tma_bulk(pbuf_u32 + ((k + 1) & 1) * (PB_U4 * 16), g_prec + t0 * REC, bytes, b);
        }

        // wait for this chunk's records
        mbar_wait((k & 1) ? bar1 : bar0, (k >> 1) & 1);

        // compute this chunk: one warp per node, lane = column.
        // Next-slot record head is prefetched into registers BEFORE the
        // activation store so its LDS issues under the current tanh chain.
        int s0 = s_lv[k], s1 = s_lv[k + 1];
        const uint4* rec = pbuf + (k & 1) * PB_U4;
        int sl = s0 + wid;
        if (sl < s1) {
            const uint4* P = rec + (sl - s0) * REC;
            uint4 I0 = P[0], I1 = P[1], I2 = P[2], I3 = P[3];
            unsigned so = P[16].x;
            while (true) {
                int nsl = sl + NWARP;
                const uint4* Q = rec + (nsl - s0) * REC;
                uint4 J0, J1, J2, J3; unsigned nso = 0;
                if (nsl < s1) {
                    J0 = Q[0]; J1 = Q[1]; J2 = Q[2]; J3 = Q[3]; nso = Q[16].x;
                } else {
                    J0 = J1 = J2 = J3 = make_uint4(0u, 0u, 0u, 0u);
                }

                float a0, a1, a2, a3;
                // degrees 0..7 from prefetched regs
                a0 = __uint_as_float(I0.y) * *(const float*)(Acb + I0.x);
                a1 = __uint_as_float(I0.w) * *(const float*)(Acb + I0.z);
                a2 = __uint_as_float(I1.y) * *(const float*)(Acb + I1.x);
                a3 = __uint_as_float(I1.w) * *(const float*)(Acb + I1.z);
                a0 = __fmaf_rn(__uint_as_float(I2.y), *(const float*)(Acb + I2.x), a0);
                a1 = __fmaf_rn(__uint_as_float(I2.w), *(const float*)(Acb + I2.z), a1);
                a2 = __fmaf_rn(__uint_as_float(I3.y), *(const float*)(Acb + I3.x), a2);
                a3 = __fmaf_rn(__uint_as_float(I3.w), *(const float*)(Acb + I3.z), a3);
                // degrees 8..31 from SMEM record
                #pragma unroll
                for (int j = 4; j < 16; j += 2) {
                    uint4 p = P[j], q = P[j + 1];
                    a0 = __fmaf_rn(__uint_as_float(p.y), *(const float*)(Acb + p.x), a0);
                    a1 = __fmaf_rn(__uint_as_float(p.w), *(const float*)(Acb + p.z), a1);
                    a2 = __fmaf_rn(__uint_as_float(q.y), *(const float*)(Acb + q.x), a2);
                    a3 = __fmaf_rn(__uint_as_float(q.w), *(const float*)(Acb + q.z), a3);
                }
                float t = ftanh((a0 + a2) + (a1 + a3));
                *(float*)((char*)As + so + (lane << 2)) = t;    // conflict-free row store

                if (nsl >= s1) break;
                sl = nsl;  P = Q;
                I0 = J0; I1 = J1; I2 = J2; I3 = J3;  so = nso;
            }
        }

        __syncthreads();
    }

    // ---- emit last OUT_SIZE node rows (by original id): out[o][b0+c] ----
    for (int e = tid; e < OUT_SIZE * BT; e += NTHR) {
        int o = e >> 5, c = e & 31;
        float v = As[(IN_SIZE + N_NODES - OUT_SIZE + o) * BT + c];
        out[(size_t)o * BATCH + b0 + c] = v;
    }
}

extern "C" void kernel_launch(void* const* d_in, const int* in_sizes, int n_in,
                              void* d_out, int out_size) {
    const float* x   = (const float*)d_in[0];   // [16384, 256] f32
    const float* w   = (const float*)d_in[1];   // [1024, 32]   f32
    const int*   idx = (const int*)  d_in[2];   // [1024, 32]   i32
    float*       out = (float*)d_out;           // [16, 16384]  f32

    cudaFuncSetAttribute(schedule_kernel, cudaFuncAttributeMaxDynamicSharedMemorySize, PA_SMEM);
    cudaFuncSetAttribute(ne_kernel, cudaFuncAttributeMaxDynamicSharedMemorySize, SMEM_BYTES);

    schedule_kernel<<<1, PA_NTHR, PA_SMEM>>>(idx, w);
    ne_kernel<<<NCTA, NTHR, SMEM_BYTES>>>(x, out);
}

// round 16
// speedup vs baseline: 1.2847x; 1.0022x over previous
#include <cuda_runtime.h>
#include <cstdint>

#define IN_SIZE  256
#define N_NODES  1024
#define DEG      32
#define BATCH    16384
#define OUT_SIZE 16

#define BT      32                      // batch columns per CTA (= warp width)
#define NTHR    384                     // 12 warps (R8-proven optimum)
#define NWARP   12
#define NROWS   (IN_SIZE + N_NODES)     // 1280
#define NCTA    (BATCH / BT)            // 512
#define REC     17                      // uint4/node: 16 (off,w,off,w) + 1 meta
#define PB_NODES 64                     // max nodes per level chunk
#define PB_U4   (PB_NODES * REC)        // 1088 uint4 per buffer
#define AS_FLOATS (NROWS * BT)          // 40960 (row stride 32 words = 128 B)
#define MAXB    1100
// layout: As | pbuf(2) | mbar(2 u64) | s_lv
#define SMEM_BYTES (AS_FLOATS * 4 + 2 * PB_U4 * 16 + 16 + (MAXB + 4) * 4)

// ---------------- device globals ----------------
__device__ int   g_sched[N_NODES];      // slot -> node id (level-grouped)
__device__ int   g_nlvl;                // number of level chunks
__device__ int   g_lvloff[MAXB];        // chunk boundaries B[0..nlvl]
__device__ uint4 g_prec[N_NODES * REC]; // slot-major packed node records

// ---------------- prepass: depth + schedule + pack (1 block, 1024 thr) ----------------
__device__ __forceinline__ int redmax32(int v) {
    int r;
    asm("redux.sync.max.s32 %0, %1, 0xffffffff;" : "=r"(r) : "r"(v));
    return r;
}

#define PA_NTHR 1024
#define PA_SMEM ((32768 + 1280 + 1025 + 1025 + 2) * 4)

__global__ void schedule_kernel(const int* __restrict__ idx, const float* __restrict__ w) {
    extern __shared__ int sm[];
    int* s_idx = sm;                    // [1024*32]
    int* s_dep = sm + 32768;            // [1280] depth per activation row
    int* s_cnt = s_dep + 1280;          // [1025] level histogram
    int* s_off = s_cnt + 1025;          // [1025] level start slot (placement cursor)
    int* s_aux = s_off + 1025;          // [1]: maxd
    const int tid = threadIdx.x;

    {   // stage idx; init
        const int4* src = (const int4*)idx;
        int4* dst = (int4*)s_idx;
        for (int i = tid; i < 8192; i += PA_NTHR) dst[i] = src[i];
        if (tid < 256)  s_dep[tid] = 0;
        for (int i = tid; i < 1025; i += PA_NTHR) s_cnt[i] = 0;
        if (tid == 0) s_aux[0] = 0;
    }
    __syncthreads();

    // ---- sequential depth, 4-node speculative window (warp 0) ----
    if (tid < 32) {
        const int lane = tid;
        for (int base = 0; base < N_NODES; base += 4) {
            const int lim = IN_SIZE + base;
            int r0 = s_idx[(base + 0) * 32 + lane];
            int r1 = s_idx[(base + 1) * 32 + lane];
            int r2 = s_idx[(base + 2) * 32 + lane];
            int r3 = s_idx[(base + 3) * 32 + lane];
            int v0 = (r0 < lim) ? s_dep[r0] : 0;   // in-window refs patched below
            int v1 = (r1 < lim) ? s_dep[r1] : 0;
            int v2 = (r2 < lim) ? s_dep[r2] : 0;
            int v3 = (r3 < lim) ? s_dep[r3] : 0;
            int m0 = redmax32(v0), m1 = redmax32(v1);
            int m2 = redmax32(v2), m3 = redmax32(v3);
            bool b10 = __any_sync(0xffffffffu, r1 == lim);
            bool b20 = __any_sync(0xffffffffu, r2 == lim);
            bool b21 = __any_sync(0xffffffffu, r2 == lim + 1);
            bool b30 = __any_sync(0xffffffffu, r3 == lim);
            bool b31 = __any_sync(0xffffffffu, r3 == lim + 1);
            bool b32 = __any_sync(0xffffffffu, r3 == lim + 2);
            int d0 = m0 + 1;
            int d1 = max(m1, b10 ? d0 : 0) + 1;
            int d2 = max(max(m2, b20 ? d0 : 0), b21 ? d1 : 0) + 1;
            int d3 = max(max(m3, b30 ? d0 : 0), max(b31 ? d1 : 0, b32 ? d2 : 0)) + 1;
            if (lane == 0) {
                s_dep[lim]     = d0;  s_dep[lim + 1] = d1;
                s_dep[lim + 2] = d2;  s_dep[lim + 3] = d3;
            }
            __syncwarp();   // order lane0's STS before next window's cross-lane LDS
        }
    }
    __syncthreads();

    // ---- level histogram + max level ----
    if (tid < N_NODES) {
        int l = s_dep[IN_SIZE + tid];
        atomicAdd(&s_cnt[l], 1);
        atomicMax(&s_aux[0], l);
    }
    __syncthreads();

    // ---- level starts + chunked boundaries (<= PB_NODES per chunk) ----
    if (tid == 0) {
        int acc = 0, nb = 0, md = s_aux[0];
        g_lvloff[0] = 0;
        for (int l = 1; l <= md; l++) {
            s_off[l] = acc;
            int c = s_cnt[l];
            while (c > 0) {
                int take = (c < PB_NODES) ? c : PB_NODES;
                acc += take;  c -= take;
                g_lvloff[++nb] = acc;
            }
        }
        g_nlvl = nb;
    }
    __syncthreads();

    // ---- stable placement (warp 0, match_any) ----
    if (tid < 32) {
        const int lane = tid;
        for (int c = 0; c < 32; c++) {
            int i = c * 32 + lane;
            int l = s_dep[IN_SIZE + i];
            unsigned mask = __match_any_sync(0xffffffffu, l);
            int rank = __popc(mask & ((1u << lane) - 1u));
            int base_ = s_off[l];
            g_sched[base_ + rank] = i;
            if ((int)(__ffs(mask) - 1) == lane) s_off[l] = base_ + __popc(mask);
            __syncwarp();
        }
    }
    __syncthreads();

    // ---- fused pack, 17-uint4 records (R8 format) ----
    // j<16: { off(2j), w(2j), off(2j+1), w(2j+1) }, off = row*128 (byte offset)
    // j=16: { store byte offset, 0,0,0 }
    for (int e = tid; e < N_NODES * REC; e += PA_NTHR) {
        int s = e / REC, j = e - s * REC;
        int node = g_sched[s];
        if (j < 16) {
            int d0 = 2 * j;
            g_prec[e] = make_uint4((unsigned)s_idx[node * DEG + d0]     << 7,
                                   __float_as_uint(w[node * DEG + d0]),
                                   (unsigned)s_idx[node * DEG + d0 + 1] << 7,
                                   __float_as_uint(w[node * DEG + d0 + 1]));
        } else {
            g_prec[e] = make_uint4((unsigned)(IN_SIZE + node) << 7, 0u, 0u, 0u);
        }
    }
}

// Exact tanh(x) = 1 - 2/(exp(2x)+1); ~1e-6 abs err, saturates correctly.
__device__ __forceinline__ float ftanh(float x) {
    float e = __expf(2.0f * x);
    return 1.0f - __fdividef(2.0f, e + 1.0f);
}

// ---- TMA bulk + mbarrier helpers ----
__device__ __forceinline__ void mbar_init(unsigned bar, unsigned cnt) {
    asm volatile("mbarrier.init.shared.b64 [%0], %1;" :: "r"(bar), "r"(cnt) : "memory");
}
__device__ __forceinline__ void mbar_expect_tx(unsigned bar, unsigned bytes) {
    asm volatile("mbarrier.arrive.expect_tx.shared.b64 _, [%0], %1;"
                 :: "r"(bar), "r"(bytes) : "memory");
}
__device__ __forceinline__ void mbar_wait(unsigned bar, unsigned phase) {
    asm volatile(
        "{\n\t.reg .pred P;\n"
        "WAIT_%=:\n\t"
        "mbarrier.try_wait.parity.acquire.cta.shared::cta.b64 P, [%0], %1;\n\t"
        "@P bra DONE_%=;\n\t"
        "bra WAIT_%=;\n"
        "DONE_%=:\n\t}"
        :: "r"(bar), "r"(phase) : "memory");
}
__device__ __forceinline__ void tma_bulk(unsigned dst, const void* src,
                                         unsigned bytes, unsigned bar) {
    asm volatile(
        "cp.async.bulk.shared::cta.global.mbarrier::complete_tx::bytes [%0], [%1], %2, [%3];"
        :: "r"(dst), "l"(src), "r"(bytes), "r"(bar) : "memory");
}

extern __shared__ float SM[];

__global__ void __launch_bounds__(NTHR, 1)
ne_kernel(const float* __restrict__ x, float* __restrict__ out) {
    const int tid  = threadIdx.x;
    const int lane = tid & 31;
    const int wid  = tid >> 5;
    const int b0   = blockIdx.x * BT;

    float* As   = SM;                                   // [1280][32] floats, row = 128 B
    uint4* pbuf = (uint4*)(SM + AS_FLOATS);             // 2 x PB_U4
    unsigned sm_base = (unsigned)__cvta_generic_to_shared(SM);
    const unsigned pbuf_u32 = sm_base + AS_FLOATS * 4;
    const unsigned bar0 = pbuf_u32 + 2 * PB_U4 * 16;    // 16B-aligned
    const unsigned bar1 = bar0 + 8;
    int* s_lv = (int*)((char*)pbuf + 2 * PB_U4 * 16 + 16);

    const int nb = g_nlvl;

    if (tid == 0) { mbar_init(bar0, 1); mbar_init(bar1, 1); }

    // ---- stage inputs transposed: As[row][col] = x[b0+col][row]; cache boundaries ----
    {
        for (int t = tid; t < BT * (IN_SIZE / 4); t += NTHR) {
            int bl = t >> 6;            // 0..31 column
            int k  = t & 63;            // float4 chunk within row
            float4 v = ((const float4*)(x + (size_t)(b0 + bl) * IN_SIZE))[k];
            int i = k * 4;
            As[(i + 0) * BT + bl] = v.x;
            As[(i + 1) * BT + bl] = v.y;
            As[(i + 2) * BT + bl] = v.z;
            As[(i + 3) * BT + bl] = v.w;
        }
        for (int i = tid; i <= nb; i += NTHR) s_lv[i] = g_lvloff[i];
    }
    __syncthreads();   // mbar init + staged data visible to all

    char* Acb = (char*)As + (lane << 2);    // this lane's column base

    // ---- prologue: TMA chunk 0 into buffer 0 ----
    if (tid == 0) {
        unsigned bytes = (unsigned)(s_lv[1] - s_lv[0]) * (REC * 16);
        mbar_expect_tx(bar0, bytes);
        tma_bulk(pbuf_u32, g_prec, bytes, bar0);
    }

    // ---- level-chunk loop ----
    for (int k = 0; k < nb; k++) {
        // stage next chunk into the other buffer (overlapped with compute)
        if (tid == 0 && k + 1 < nb) {
            int t0 = s_lv[k + 1], t1 = s_lv[k + 2];
            unsigned bytes = (unsigned)(t1 - t0) * (REC * 16);
            unsigned b = ((k + 1) & 1) ? bar1 : bar0;
            mbar_expect_tx(b, bytes);
            tma_bulk(pbuf_u32 + ((k + 1) & 1) * (PB_U4 * 16), g_prec + t0 * REC, bytes, b);
        }

        // wait for this chunk's records
        mbar_wait((k & 1) ? bar1 : bar0, (k >> 1) & 1);

        // compute this chunk: one warp per node, lane = column.
        // Next-slot record head is prefetched into registers BEFORE the
        // activation store so its LDS issues under the current tanh chain.
        int s0 = s_lv[k], s1 = s_lv[k + 1];
        const uint4* rec = pbuf + (k & 1) * PB_U4;
        int sl = s0 + wid;
        if (sl < s1) {
            const uint4* P = rec + (sl - s0) * REC;
            uint4 I0 = P[0], I1 = P[1], I2 = P[2], I3 = P[3];
            unsigned so = P[16].x;
            while (true) {
                int nsl = sl + NWARP;
                const uint4* Q = rec + (nsl - s0) * REC;
                uint4 J0, J1, J2, J3; unsigned nso = 0;
                if (nsl < s1) {
                    J0 = Q[0]; J1 = Q[1]; J2 = Q[2]; J3 = Q[3]; nso = Q[16].x;
                } else {
                    J0 = J1 = J2 = J3 = make_uint4(0u, 0u, 0u, 0u);
                }

                float a0, a1, a2, a3;
                // degrees 0..7 from prefetched regs
                a0 = __uint_as_float(I0.y) * *(const float*)(Acb + I0.x);
                a1 = __uint_as_float(I0.w) * *(const float*)(Acb + I0.z);
                a2 = __uint_as_float(I1.y) * *(const float*)(Acb + I1.x);
                a3 = __uint_as_float(I1.w) * *(const float*)(Acb + I1.z);
                a0 = __fmaf_rn(__uint_as_float(I2.y), *(const float*)(Acb + I2.x), a0);
                a1 = __fmaf_rn(__uint_as_float(I2.w), *(const float*)(Acb + I2.z), a1);
                a2 = __fmaf_rn(__uint_as_float(I3.y), *(const float*)(Acb + I3.x), a2);
                a3 = __fmaf_rn(__uint_as_float(I3.w), *(const float*)(Acb + I3.z), a3);
                // degrees 8..31 from SMEM record
                #pragma unroll
                for (int j = 4; j < 16; j += 2) {
                    uint4 p = P[j], q = P[j + 1];
                    a0 = __fmaf_rn(__uint_as_float(p.y), *(const float*)(Acb + p.x), a0);
                    a1 = __fmaf_rn(__uint_as_float(p.w), *(const float*)(Acb + p.z), a1);
                    a2 = __fmaf_rn(__uint_as_float(q.y), *(const float*)(Acb + q.x), a2);
                    a3 = __fmaf_rn(__uint_as_float(q.w), *(const float*)(Acb + q.z), a3);
                }
                float t = ftanh((a0 + a2) + (a1 + a3));
                *(float*)((char*)As + so + (lane << 2)) = t;    // conflict-free row store

                if (nsl >= s1) break;
                sl = nsl;  P = Q;
                I0 = J0; I1 = J1; I2 = J2; I3 = J3;  so = nso;
            }
        }

        __syncthreads();
    }

    // ---- emit last OUT_SIZE node rows (by original id): out[o][b0+c] ----
    for (int e = tid; e < OUT_SIZE * BT; e += NTHR) {
        int o = e >> 5, c = e & 31;
        float v = As[(IN_SIZE + N_NODES - OUT_SIZE + o) * BT + c];
        out[(size_t)o * BATCH + b0 + c] = v;
    }
}

extern "C" void kernel_launch(void* const* d_in, const int* in_sizes, int n_in,
                              void* d_out, int out_size) {
    const float* x   = (const float*)d_in[0];   // [16384, 256] f32
    const float* w   = (const float*)d_in[1];   // [1024, 32]   f32
    const int*   idx = (const int*)  d_in[2];   // [1024, 32]   i32
    float*       out = (float*)d_out;           // [16, 16384]  f32

    cudaFuncSetAttribute(schedule_kernel, cudaFuncAttributeMaxDynamicSharedMemorySize, PA_SMEM);
    cudaFuncSetAttribute(ne_kernel, cudaFuncAttributeMaxDynamicSharedMemorySize, SMEM_BYTES);

    schedule_kernel<<<1, PA_NTHR, PA_SMEM>>>(idx, w);
    ne_kernel<<<NCTA, NTHR, SMEM_BYTES>>>(x, out);
}